// round 5
// baseline (speedup 1.0000x reference)
#include <cuda_runtime.h>

#define N_NODES 100000
#define N_EDGES 1600000
#define N_LAB   200000
#define D       128
#define D4      32   // D/4

// ---------------- static device scratch (no allocations allowed) ----------
__device__ float g_h[(size_t)N_NODES * D];   // GEMM output (pre-aggregation)
__device__ float g_z[(size_t)N_NODES * D];   // aggregated features
__device__ float g_dinv[N_NODES];
__device__ int   g_deg[N_NODES];
__device__ int   g_src[N_EDGES];
__device__ int   g_dst[N_EDGES];
__device__ float g_w[N_EDGES];
__device__ int   g_is64;                     // 1 if edge indices are int64

// ---------------- dtype autodetect ----------------------------------------
// For int64 node indices (< 2^31, little-endian) every odd 32-bit word is 0.
// For int32 data the odd words are random node ids. 32 samples → P(err)≈0.
__global__ void k_detect(const int* __restrict__ ei_raw) {
    if (threadIdx.x == 0 && blockIdx.x == 0) {
        int all_zero = 1;
        for (int i = 0; i < 32; i++)
            if (ei_raw[2 * i + 1] != 0) { all_zero = 0; break; }
        g_is64 = all_zero;
    }
}

__device__ __forceinline__ int load_idx(const void* p, size_t i) {
    return g_is64 ? (int)((const long long*)p)[i] : ((const int*)p)[i];
}

// ---------------- degree / norm prep --------------------------------------
__global__ void k_deg_init() {
    int i = blockIdx.x * blockDim.x + threadIdx.x;
    if (i < N_NODES) g_deg[i] = 1;   // self loop
}

__global__ void k_deg_acc(const void* __restrict__ ei) {
    int e = blockIdx.x * blockDim.x + threadIdx.x;
    if (e < N_EDGES) {
        int d = load_idx(ei, (size_t)N_EDGES + e);
        atomicAdd(&g_deg[d], 1);
    }
}

__global__ void k_dinv() {
    int i = blockIdx.x * blockDim.x + threadIdx.x;
    if (i < N_NODES) g_dinv[i] = rsqrtf((float)g_deg[i]);
}

__global__ void k_prep(const void* __restrict__ ei) {
    int e = blockIdx.x * blockDim.x + threadIdx.x;
    if (e < N_EDGES) {
        int s = load_idx(ei, e);
        int d = load_idx(ei, (size_t)N_EDGES + e);
        g_src[e] = s;
        g_dst[e] = d;
        g_w[e]   = g_dinv[s] * g_dinv[d];
    }
}

// ---------------- GEMM: C[M,128] = act(A + pre_bias) @ W -------------------
// Block: 256 threads, 64-row tile, full 128-col width. W + X tile in smem.
// pre_bias/relu applied to the *input* tile (fuses layer-1 epilogue into
// layer-2 GEMM load).
__global__ void __launch_bounds__(256, 2)
k_gemm(const float* __restrict__ A, const float* __restrict__ W,
       const float* __restrict__ pre_bias, int do_relu,
       float* __restrict__ C, int M) {
    extern __shared__ float sm[];
    float* Ws = sm;            // 128*128
    float* Xs = sm + D * D;    // 64*128
    int tid = threadIdx.x;
    int row_base = blockIdx.x * 64;

    // load W (16384 floats = 4096 float4)
    for (int i = tid; i < D * D4; i += 256)
        ((float4*)Ws)[i] = ((const float4*)W)[i];

    // load X tile (64x128 = 2048 float4), fusing optional bias+relu
    for (int i = tid; i < 64 * D4; i += 256) {
        int r  = i >> 5;        // /32
        int c4 = i & 31;
        int gr = row_base + r;
        float4 v = make_float4(0.f, 0.f, 0.f, 0.f);
        if (gr < M) v = ((const float4*)A)[(size_t)gr * D4 + c4];
        if (pre_bias) {
            float4 b = ((const float4*)pre_bias)[c4];
            v.x += b.x; v.y += b.y; v.z += b.z; v.w += b.w;
            if (do_relu) {
                v.x = fmaxf(v.x, 0.f); v.y = fmaxf(v.y, 0.f);
                v.z = fmaxf(v.z, 0.f); v.w = fmaxf(v.w, 0.f);
            }
        }
        ((float4*)Xs)[i] = v;
    }
    __syncthreads();

    int tx = tid & 31;          // 32 col-groups
    int ty = tid >> 5;          // 8 row-groups
    int col0 = tx * 4;
    int row0 = ty * 8;

    float acc[8][4];
#pragma unroll
    for (int i = 0; i < 8; i++)
#pragma unroll
        for (int j = 0; j < 4; j++) acc[i][j] = 0.f;

#pragma unroll 4
    for (int k = 0; k < D; ++k) {
        float4 bv = *(const float4*)(Ws + k * D + col0);
#pragma unroll
        for (int i = 0; i < 8; i++) {
            float a = Xs[(row0 + i) * D + k];   // warp-broadcast
            acc[i][0] = fmaf(a, bv.x, acc[i][0]);
            acc[i][1] = fmaf(a, bv.y, acc[i][1]);
            acc[i][2] = fmaf(a, bv.z, acc[i][2]);
            acc[i][3] = fmaf(a, bv.w, acc[i][3]);
        }
    }

#pragma unroll
    for (int i = 0; i < 8; i++) {
        int gr = row_base + row0 + i;
        if (gr < M)
            *(float4*)(C + (size_t)gr * D + col0) =
                make_float4(acc[i][0], acc[i][1], acc[i][2], acc[i][3]);
    }
}

// ---------------- self-loop init: z[i] = h[i] * dinv[i]^2 ------------------
__global__ void k_selfinit() {
    int t = blockIdx.x * blockDim.x + threadIdx.x;   // one float4 per thread
    if (t < N_NODES * D4) {
        int node = t >> 5;
        float di = g_dinv[node];
        float w = di * di;
        float4 v = ((const float4*)g_h)[t];
        ((float4*)g_z)[t] = make_float4(v.x * w, v.y * w, v.z * w, v.w * w);
    }
}

// ---------------- edge aggregation: z[dst] += h[src] * w -------------------
// One warp per edge; each lane handles 4 consecutive floats. Scalar
// atomicAdd compiles to REDG.F32 (no return) — fast on the LTS atomic ALU.
__global__ void __launch_bounds__(256) k_agg() {
    int gwarp  = (blockIdx.x * blockDim.x + threadIdx.x) >> 5;
    int lane   = threadIdx.x & 31;
    int nwarps = (gridDim.x * blockDim.x) >> 5;
    for (int e = gwarp; e < N_EDGES; e += nwarps) {
        int s = g_src[e];
        int d = g_dst[e];
        float w = g_w[e];
        float4 v = ((const float4*)g_h)[(size_t)s * D4 + lane];
        float* addr = g_z + (size_t)d * D + lane * 4;
        atomicAdd(addr + 0, v.x * w);
        atomicAdd(addr + 1, v.y * w);
        atomicAdd(addr + 2, v.z * w);
        atomicAdd(addr + 3, v.w * w);
    }
}

// ---------------- decode: logits[e] = dot(z[s]+b2, z[d]+b2) ----------------
__global__ void __launch_bounds__(256) k_decode(const void* __restrict__ lab,
                                                const float* __restrict__ b2,
                                                float* __restrict__ out) {
    int gwarp  = (blockIdx.x * blockDim.x + threadIdx.x) >> 5;
    int lane   = threadIdx.x & 31;
    int nwarps = (gridDim.x * blockDim.x) >> 5;
    float4 b = ((const float4*)b2)[lane];
    for (int e = gwarp; e < N_LAB; e += nwarps) {
        int s = load_idx(lab, e);
        int d = load_idx(lab, (size_t)N_LAB + e);
        float4 a = ((const float4*)g_z)[(size_t)s * D4 + lane];
        float4 c = ((const float4*)g_z)[(size_t)d * D4 + lane];
        float sum = (a.x + b.x) * (c.x + b.x)
                  + (a.y + b.y) * (c.y + b.y)
                  + (a.z + b.z) * (c.z + b.z)
                  + (a.w + b.w) * (c.w + b.w);
#pragma unroll
        for (int off = 16; off; off >>= 1)
            sum += __shfl_xor_sync(0xFFFFFFFFu, sum, off);
        if (lane == 0) out[e] = sum;
    }
}

// ---------------- launch ---------------------------------------------------
extern "C" void kernel_launch(void* const* d_in, const int* in_sizes, int n_in,
                              void* d_out, int out_size) {
    const float* x   = (const float*)d_in[0];
    const void*  ei  = d_in[1];               // int32 or int64, autodetected
    const void*  lab = d_in[2];
    const float* W1  = (const float*)d_in[3];
    const float* b1  = (const float*)d_in[4];
    const float* W2  = (const float*)d_in[5];
    const float* b2  = (const float*)d_in[6];
    float*       out = (float*)d_out;

    (void)in_sizes; (void)n_in; (void)out_size;

    const int SMEM = (D * D + 64 * D) * (int)sizeof(float);  // 98304 B
    cudaFuncSetAttribute(k_gemm, cudaFuncAttributeMaxDynamicSharedMemorySize, SMEM);

    float *hptr = nullptr, *zptr = nullptr;
    cudaGetSymbolAddress((void**)&hptr, g_h);
    cudaGetSymbolAddress((void**)&zptr, g_z);

    const int T = 256;
    // dtype detect + normalization prep
    k_detect  <<<1, 32>>>((const int*)ei);
    k_deg_init<<<(N_NODES + T - 1) / T, T>>>();
    k_deg_acc <<<(N_EDGES + T - 1) / T, T>>>(ei);
    k_dinv    <<<(N_NODES + T - 1) / T, T>>>();
    k_prep    <<<(N_EDGES + T - 1) / T, T>>>(ei);

    const int GEMM_BLOCKS = (N_NODES + 63) / 64;
    const int AGG_BLOCKS  = 1184;   // 148 SMs * 8
    const int SI_BLOCKS   = (N_NODES * D4 + T - 1) / T;

    // layer 1: h = x @ W1 ; z = sum_norm(h) (bias+relu deferred into GEMM2 load)
    k_gemm<<<GEMM_BLOCKS, T, SMEM>>>(x, W1, nullptr, 0, hptr, N_NODES);
    k_selfinit<<<SI_BLOCKS, T>>>();
    k_agg<<<AGG_BLOCKS, T>>>();

    // layer 2: h = relu(z + b1) @ W2 ; z = sum_norm(h)  (b2 fused into decode)
    k_gemm<<<GEMM_BLOCKS, T, SMEM>>>(zptr, W2, b1, 1, hptr, N_NODES);
    k_selfinit<<<SI_BLOCKS, T>>>();
    k_agg<<<AGG_BLOCKS, T>>>();

    // decode
    k_decode<<<AGG_BLOCKS, T>>>(lab, b2, out);
}

// round 6
// speedup vs baseline: 2.9175x; 2.9175x over previous
#include <cuda_runtime.h>

#define N_NODES 100000
#define N_EDGES 1600000
#define N_LAB   200000
#define D       128
#define D4      32   // D/4
#define NB      391  // ceil(N_NODES / 256)

// ---------------- static device scratch (no allocations allowed) ----------
__device__ float g_h[(size_t)N_NODES * D];   // GEMM output (pre-aggregation)
__device__ float g_z[(size_t)N_NODES * D];   // aggregated features
__device__ float g_dinv[N_NODES];
__device__ int   g_cnt[N_NODES];             // in-degree (edges only)
__device__ int   g_rowptr[N_NODES + 1];
__device__ int   g_cursor[N_NODES];
__device__ int   g_bsum[NB];
__device__ int   g_boff[NB];
__device__ int2  g_csr[N_EDGES];             // {src, bitcast(norm weight)}
__device__ int   g_is64;                     // 1 if edge indices are int64

// ---------------- dtype autodetect ----------------------------------------
// int64 node indices (< 2^31, LE): every odd 32-bit word is 0. For int32
// data the odd words are random node ids. 32 samples → P(err) ≈ 0.
__global__ void k_detect(const int* __restrict__ ei_raw) {
    if (threadIdx.x == 0 && blockIdx.x == 0) {
        int all_zero = 1;
        for (int i = 0; i < 32; i++)
            if (ei_raw[2 * i + 1] != 0) { all_zero = 0; break; }
        g_is64 = all_zero;
    }
}

__device__ __forceinline__ int load_idx(const void* p, size_t i) {
    return g_is64 ? (int)((const long long*)p)[i] : ((const int*)p)[i];
}

// ---------------- degree / norm prep --------------------------------------
__global__ void k_cnt_init() {
    int i = blockIdx.x * blockDim.x + threadIdx.x;
    if (i < N_NODES) g_cnt[i] = 0;
}

__global__ void k_cnt_acc(const void* __restrict__ ei) {
    int e = blockIdx.x * blockDim.x + threadIdx.x;
    if (e < N_EDGES) atomicAdd(&g_cnt[load_idx(ei, (size_t)N_EDGES + e)], 1);
}

__global__ void k_dinv() {
    int i = blockIdx.x * blockDim.x + threadIdx.x;
    if (i < N_NODES) g_dinv[i] = rsqrtf((float)(g_cnt[i] + 1));  // +1 self loop
}

// ---------------- CSR build: 3-kernel prefix sum + binned fill -------------
__global__ void k_scan_block() {
    __shared__ int sm[256];
    int b = blockIdx.x, t = threadIdx.x;
    int i = b * 256 + t;
    int v = (i < N_NODES) ? g_cnt[i] : 0;
    sm[t] = v;
    __syncthreads();
    for (int off = 1; off < 256; off <<= 1) {
        int add = (t >= off) ? sm[t - off] : 0;
        __syncthreads();
        sm[t] += add;
        __syncthreads();
    }
    if (i < N_NODES) g_rowptr[i] = sm[t] - v;   // local exclusive
    if (t == 255)    g_bsum[b] = sm[255];
}

__global__ void k_scan_top() {
    __shared__ int sm[512];
    int t = threadIdx.x;
    int v = (t < NB) ? g_bsum[t] : 0;
    sm[t] = v;
    __syncthreads();
    for (int off = 1; off < 512; off <<= 1) {
        int add = (t >= off) ? sm[t - off] : 0;
        __syncthreads();
        sm[t] += add;
        __syncthreads();
    }
    if (t < NB) g_boff[t] = sm[t] - v;          // exclusive block offsets
    if (t == 0) g_rowptr[N_NODES] = sm[511];    // total edge count
}

__global__ void k_scan_add() {
    int i = blockIdx.x * blockDim.x + threadIdx.x;
    if (i < N_NODES) {
        int r = g_rowptr[i] + g_boff[i >> 8];
        g_rowptr[i] = r;
        g_cursor[i] = r;
    }
}

__global__ void k_fill(const void* __restrict__ ei) {
    int e = blockIdx.x * blockDim.x + threadIdx.x;
    if (e < N_EDGES) {
        int s = load_idx(ei, e);
        int d = load_idx(ei, (size_t)N_EDGES + e);
        float w = g_dinv[s] * g_dinv[d];
        int pos = atomicAdd(&g_cursor[d], 1);
        g_csr[pos] = make_int2(s, __float_as_int(w));
    }
}

// ---------------- GEMM: C[M,128] = act(A + pre_bias) @ W -------------------
__global__ void __launch_bounds__(256, 2)
k_gemm(const float* __restrict__ A, const float* __restrict__ W,
       const float* __restrict__ pre_bias, int do_relu,
       float* __restrict__ C, int M) {
    extern __shared__ float sm[];
    float* Ws = sm;            // 128*128
    float* Xs = sm + D * D;    // 64*128
    int tid = threadIdx.x;
    int row_base = blockIdx.x * 64;

    for (int i = tid; i < D * D4; i += 256)
        ((float4*)Ws)[i] = ((const float4*)W)[i];

    for (int i = tid; i < 64 * D4; i += 256) {
        int r  = i >> 5;
        int c4 = i & 31;
        int gr = row_base + r;
        float4 v = make_float4(0.f, 0.f, 0.f, 0.f);
        if (gr < M) v = ((const float4*)A)[(size_t)gr * D4 + c4];
        if (pre_bias) {
            float4 b = ((const float4*)pre_bias)[c4];
            v.x += b.x; v.y += b.y; v.z += b.z; v.w += b.w;
            if (do_relu) {
                v.x = fmaxf(v.x, 0.f); v.y = fmaxf(v.y, 0.f);
                v.z = fmaxf(v.z, 0.f); v.w = fmaxf(v.w, 0.f);
            }
        }
        ((float4*)Xs)[i] = v;
    }
    __syncthreads();

    int tx = tid & 31;
    int ty = tid >> 5;
    int col0 = tx * 4;
    int row0 = ty * 8;

    float acc[8][4];
#pragma unroll
    for (int i = 0; i < 8; i++)
#pragma unroll
        for (int j = 0; j < 4; j++) acc[i][j] = 0.f;

#pragma unroll 4
    for (int k = 0; k < D; ++k) {
        float4 bv = *(const float4*)(Ws + k * D + col0);
#pragma unroll
        for (int i = 0; i < 8; i++) {
            float a = Xs[(row0 + i) * D + k];
            acc[i][0] = fmaf(a, bv.x, acc[i][0]);
            acc[i][1] = fmaf(a, bv.y, acc[i][1]);
            acc[i][2] = fmaf(a, bv.z, acc[i][2]);
            acc[i][3] = fmaf(a, bv.w, acc[i][3]);
        }
    }

#pragma unroll
    for (int i = 0; i < 8; i++) {
        int gr = row_base + row0 + i;
        if (gr < M)
            *(float4*)(C + (size_t)gr * D + col0) =
                make_float4(acc[i][0], acc[i][1], acc[i][2], acc[i][3]);
    }
}

// ---------------- CSR aggregation: z[n] = sum_{e->n} h[src]*w + self -------
// One warp per node. Lanes cooperatively load 32 packed edges (LDG.64),
// broadcast via shfl; each lane accumulates its own 4 feature columns.
// Atomic-free; fuses the self-loop init.
__global__ void __launch_bounds__(256)
k_agg_csr(const float* __restrict__ h, float* __restrict__ z) {
    int gw   = (blockIdx.x * blockDim.x + threadIdx.x) >> 5;
    int lane = threadIdx.x & 31;
    if (gw >= N_NODES) return;
    int n = gw;

    float di = g_dinv[n];
    float ws = di * di;                         // self-loop weight
    float4 hv = ((const float4*)h)[(size_t)n * D4 + lane];
    float4 acc = make_float4(hv.x * ws, hv.y * ws, hv.z * ws, hv.w * ws);

    int s0 = g_rowptr[n];
    int s1 = g_rowptr[n + 1];
    for (int base = s0; base < s1; base += 32) {
        int i = base + lane;
        int2 ed = (i < s1) ? g_csr[i] : make_int2(0, 0);
        int cnt = min(32, s1 - base);
        for (int j = 0; j < cnt; j++) {
            int   sj = __shfl_sync(0xFFFFFFFFu, ed.x, j);
            float wj = __int_as_float(__shfl_sync(0xFFFFFFFFu, ed.y, j));
            float4 v = ((const float4*)h)[(size_t)sj * D4 + lane];
            acc.x = fmaf(v.x, wj, acc.x);
            acc.y = fmaf(v.y, wj, acc.y);
            acc.z = fmaf(v.z, wj, acc.z);
            acc.w = fmaf(v.w, wj, acc.w);
        }
    }
    ((float4*)z)[(size_t)n * D4 + lane] = acc;
}

// ---------------- decode: logits[e] = dot(z[s]+b2, z[d]+b2) ----------------
__global__ void __launch_bounds__(256) k_decode(const void* __restrict__ lab,
                                                const float* __restrict__ b2,
                                                float* __restrict__ out) {
    int gwarp  = (blockIdx.x * blockDim.x + threadIdx.x) >> 5;
    int lane   = threadIdx.x & 31;
    int nwarps = (gridDim.x * blockDim.x) >> 5;
    float4 b = ((const float4*)b2)[lane];
    for (int e = gwarp; e < N_LAB; e += nwarps) {
        int s = load_idx(lab, e);
        int d = load_idx(lab, (size_t)N_LAB + e);
        float4 a = ((const float4*)g_z)[(size_t)s * D4 + lane];
        float4 c = ((const float4*)g_z)[(size_t)d * D4 + lane];
        float sum = (a.x + b.x) * (c.x + b.x)
                  + (a.y + b.y) * (c.y + b.y)
                  + (a.z + b.z) * (c.z + b.z)
                  + (a.w + b.w) * (c.w + b.w);
#pragma unroll
        for (int off = 16; off; off >>= 1)
            sum += __shfl_xor_sync(0xFFFFFFFFu, sum, off);
        if (lane == 0) out[e] = sum;
    }
}

// ---------------- launch ---------------------------------------------------
extern "C" void kernel_launch(void* const* d_in, const int* in_sizes, int n_in,
                              void* d_out, int out_size) {
    const float* x   = (const float*)d_in[0];
    const void*  ei  = d_in[1];               // int32 or int64, autodetected
    const void*  lab = d_in[2];
    const float* W1  = (const float*)d_in[3];
    const float* b1  = (const float*)d_in[4];
    const float* W2  = (const float*)d_in[5];
    const float* b2  = (const float*)d_in[6];
    float*       out = (float*)d_out;

    (void)in_sizes; (void)n_in; (void)out_size;

    const int SMEM = (D * D + 64 * D) * (int)sizeof(float);  // 98304 B
    cudaFuncSetAttribute(k_gemm, cudaFuncAttributeMaxDynamicSharedMemorySize, SMEM);

    float *hptr = nullptr, *zptr = nullptr;
    cudaGetSymbolAddress((void**)&hptr, g_h);
    cudaGetSymbolAddress((void**)&zptr, g_z);

    const int T = 256;
    const int NODE_BLOCKS = (N_NODES + T - 1) / T;            // 391
    const int EDGE_BLOCKS = (N_EDGES + T - 1) / T;
    const int GEMM_BLOCKS = (N_NODES + 63) / 64;
    const int AGG_BLOCKS  = (N_NODES + 7) / 8;                // warp per node
    const int DEC_BLOCKS  = 1184;

    // ---- prep: dtype detect, degrees, norms, CSR build (once per call) ----
    k_detect    <<<1, 32>>>((const int*)ei);
    k_cnt_init  <<<NODE_BLOCKS, T>>>();
    k_cnt_acc   <<<EDGE_BLOCKS, T>>>(ei);
    k_dinv      <<<NODE_BLOCKS, T>>>();
    k_scan_block<<<NB, 256>>>();
    k_scan_top  <<<1, 512>>>();
    k_scan_add  <<<NODE_BLOCKS, T>>>();
    k_fill      <<<EDGE_BLOCKS, T>>>(ei);

    // ---- layer 1: h = x @ W1 ; z = sym-norm aggregate (atomic-free) -------
    k_gemm   <<<GEMM_BLOCKS, T, SMEM>>>(x, W1, nullptr, 0, hptr, N_NODES);
    k_agg_csr<<<AGG_BLOCKS, T>>>(hptr, zptr);

    // ---- layer 2: h = relu(z + b1) @ W2 ; z = aggregate (b2 in decode) ----
    k_gemm   <<<GEMM_BLOCKS, T, SMEM>>>(zptr, W2, b1, 1, hptr, N_NODES);
    k_agg_csr<<<AGG_BLOCKS, T>>>(hptr, zptr);

    // ---- decode -----------------------------------------------------------
    k_decode<<<DEC_BLOCKS, T>>>(lab, b2, out);
}

// round 8
// speedup vs baseline: 3.1165x; 1.0682x over previous
#include <cuda_runtime.h>
#include <cuda_bf16.h>
#include <cstdint>

#define N_NODES 100000
#define N_EDGES 1600000
#define N_LAB   200000
#define D       128
#define D4      32   // D/4
#define NB      391  // ceil(N_NODES / 256)

// ---------------- static device scratch (no allocations allowed) ----------
__device__ float g_h[(size_t)N_NODES * D];   // GEMM output (pre-aggregation)
__device__ float g_z[(size_t)N_NODES * D];   // aggregated features
__device__ float g_dinv[N_NODES];
__device__ int   g_cnt[N_NODES];             // in-degree (edges only)
__device__ int   g_rowptr[N_NODES + 1];
__device__ int   g_cursor[N_NODES];
__device__ int   g_bsum[NB];
__device__ int   g_boff[NB];
__device__ int2  g_csr[N_EDGES];             // {src, bitcast(norm weight)}
__device__ int   g_is64;                     // 1 if edge indices are int64

// ---------------- dtype autodetect ----------------------------------------
__global__ void k_detect(const int* __restrict__ ei_raw) {
    if (threadIdx.x == 0 && blockIdx.x == 0) {
        int all_zero = 1;
        for (int i = 0; i < 32; i++)
            if (ei_raw[2 * i + 1] != 0) { all_zero = 0; break; }
        g_is64 = all_zero;
    }
}

__device__ __forceinline__ int load_idx(const void* p, size_t i) {
    return g_is64 ? (int)((const long long*)p)[i] : ((const int*)p)[i];
}

// ---------------- degree / norm prep --------------------------------------
__global__ void k_cnt_init() {
    int i = blockIdx.x * blockDim.x + threadIdx.x;
    if (i < N_NODES) g_cnt[i] = 0;
}

__global__ void k_cnt_acc(const void* __restrict__ ei) {
    int e = blockIdx.x * blockDim.x + threadIdx.x;
    if (e < N_EDGES) atomicAdd(&g_cnt[load_idx(ei, (size_t)N_EDGES + e)], 1);
}

__global__ void k_dinv() {
    int i = blockIdx.x * blockDim.x + threadIdx.x;
    if (i < N_NODES) g_dinv[i] = rsqrtf((float)(g_cnt[i] + 1));  // +1 self loop
}

// ---------------- CSR build: 3-kernel prefix sum + binned fill -------------
__global__ void k_scan_block() {
    __shared__ int sm[256];
    int b = blockIdx.x, t = threadIdx.x;
    int i = b * 256 + t;
    int v = (i < N_NODES) ? g_cnt[i] : 0;
    sm[t] = v;
    __syncthreads();
    for (int off = 1; off < 256; off <<= 1) {
        int add = (t >= off) ? sm[t - off] : 0;
        __syncthreads();
        sm[t] += add;
        __syncthreads();
    }
    if (i < N_NODES) g_rowptr[i] = sm[t] - v;
    if (t == 255)    g_bsum[b] = sm[255];
}

__global__ void k_scan_top() {
    __shared__ int sm[512];
    int t = threadIdx.x;
    int v = (t < NB) ? g_bsum[t] : 0;
    sm[t] = v;
    __syncthreads();
    for (int off = 1; off < 512; off <<= 1) {
        int add = (t >= off) ? sm[t - off] : 0;
        __syncthreads();
        sm[t] += add;
        __syncthreads();
    }
    if (t < NB) g_boff[t] = sm[t] - v;
    if (t == 0) g_rowptr[N_NODES] = sm[511];
}

__global__ void k_scan_add() {
    int i = blockIdx.x * blockDim.x + threadIdx.x;
    if (i < N_NODES) {
        int r = g_rowptr[i] + g_boff[i >> 8];
        g_rowptr[i] = r;
        g_cursor[i] = r;
    }
}

__global__ void k_fill(const void* __restrict__ ei) {
    int e = blockIdx.x * blockDim.x + threadIdx.x;
    if (e < N_EDGES) {
        int s = load_idx(ei, e);
        int d = load_idx(ei, (size_t)N_EDGES + e);
        float w = g_dinv[s] * g_dinv[d];
        int pos = atomicAdd(&g_cursor[d], 1);
        g_csr[pos] = make_int2(s, __float_as_int(w));
    }
}

// ================= HMMA GEMM (mma.sync, split-bf16 x3) =====================
// C[M,128] = act(A + pre_bias) @ W.
// CTA: 128 rows x 128 cols, 256 threads (8 warps: 4 along M x 2 along N).
// A, W converted to bf16 hi/lo in padded SMEM (stride 132 halves => <=2-way
// bank conflicts). Fragments loaded with scalar LDS.32 per the m16n8k16
// thread mapping. 3 products: Ahi*Whi + Ahi*Wlo + Alo*Whi, fp32 accum.
#define PAD   132                       // padded row stride in bf16 elements
#define PADW  66                        // in 32-bit words
#define SA_HI 0
#define SA_LO (128 * PAD)
#define SW_HI (2 * 128 * PAD)
#define SW_LO (3 * 128 * PAD)
#define MMA_SMEM (4 * 128 * PAD * 2)    // bytes = 135168

__device__ __forceinline__ void mma_bf16(float* d, const uint32_t* a,
                                         uint32_t b0, uint32_t b1) {
    asm volatile(
        "mma.sync.aligned.m16n8k16.row.col.f32.bf16.bf16.f32 "
        "{%0,%1,%2,%3}, {%4,%5,%6,%7}, {%8,%9}, {%0,%1,%2,%3};"
        : "+f"(d[0]), "+f"(d[1]), "+f"(d[2]), "+f"(d[3])
        : "r"(a[0]), "r"(a[1]), "r"(a[2]), "r"(a[3]), "r"(b0), "r"(b1));
}

__global__ void __launch_bounds__(256, 1)
k_gemm_mma(const float* __restrict__ A, const float* __restrict__ Wm,
           const float* __restrict__ pre_bias, int do_relu,
           float* __restrict__ C, int M) {
    extern __shared__ __nv_bfloat16 sm[];
    uint32_t* smw = (uint32_t*)sm;
    int tid = threadIdx.x;
    int row_base = blockIdx.x * 128;

    // ---- convert A tile to hi/lo bf16 (coalesced 4B loads) ----------------
    float bcol;
#pragma unroll 4
    for (int i = 0; i < 64; i++) {
        int idx = i * 256 + tid;          // 0..16383
        int r = idx >> 7, c = idx & 127;
        int gr = row_base + r;
        float v = (gr < M) ? A[(size_t)gr * D + c] : 0.f;
        if (pre_bias) {
            v += pre_bias[c];
            if (do_relu) v = fmaxf(v, 0.f);
        }
        __nv_bfloat16 hi = __float2bfloat16(v);
        __nv_bfloat16 lo = __float2bfloat16(v - __bfloat162float(hi));
        sm[SA_HI + r * PAD + c] = hi;
        sm[SA_LO + r * PAD + c] = lo;
    }
    (void)bcol;

    // ---- convert W, transposed to (n, k) layout ---------------------------
#pragma unroll 4
    for (int i = 0; i < 64; i++) {
        int idx = i * 256 + tid;
        int k = idx >> 7, n = idx & 127;
        float v = Wm[(size_t)k * D + n];
        __nv_bfloat16 hi = __float2bfloat16(v);
        __nv_bfloat16 lo = __float2bfloat16(v - __bfloat162float(hi));
        sm[SW_HI + n * PAD + k] = hi;
        sm[SW_LO + n * PAD + k] = lo;
    }
    __syncthreads();

    // ---- warp tiling: wid&3 -> 32-row group, wid>>2 -> 64-col group -------
    int wid  = tid >> 5, lane = tid & 31;
    int g    = lane >> 2;                 // groupid 0..7
    int t4   = lane & 3;                  // 0..3
    int m_base = (wid & 3) * 32;
    int n_base = (wid >> 2) * 64;

    float acc[2][8][4];
#pragma unroll
    for (int mt = 0; mt < 2; mt++)
#pragma unroll
        for (int nt = 0; nt < 8; nt++)
#pragma unroll
            for (int j = 0; j < 4; j++) acc[mt][nt][j] = 0.f;

#pragma unroll
    for (int ks = 0; ks < 8; ks++) {
        int kw = ks * 8 + t4;             // word index of k = ks*16 + t4*2
        uint32_t ahi[2][4], alo[2][4];
#pragma unroll
        for (int mt = 0; mt < 2; mt++) {
            int r = m_base + mt * 16 + g;
            const uint32_t* aH = smw + (SA_HI >> 1);
            const uint32_t* aL = smw + (SA_LO >> 1);
            ahi[mt][0] = aH[r * PADW + kw];
            ahi[mt][1] = aH[(r + 8) * PADW + kw];
            ahi[mt][2] = aH[r * PADW + kw + 4];
            ahi[mt][3] = aH[(r + 8) * PADW + kw + 4];
            alo[mt][0] = aL[r * PADW + kw];
            alo[mt][1] = aL[(r + 8) * PADW + kw];
            alo[mt][2] = aL[r * PADW + kw + 4];
            alo[mt][3] = aL[(r + 8) * PADW + kw + 4];
        }
#pragma unroll
        for (int nt = 0; nt < 8; nt++) {
            int n = n_base + nt * 8 + g;
            const uint32_t* bH = smw + (SW_HI >> 1);
            const uint32_t* bL = smw + (SW_LO >> 1);
            uint32_t bh0 = bH[n * PADW + kw];
            uint32_t bh1 = bH[n * PADW + kw + 4];
            uint32_t bl0 = bL[n * PADW + kw];
            uint32_t bl1 = bL[n * PADW + kw + 4];
#pragma unroll
            for (int mt = 0; mt < 2; mt++) {
                mma_bf16(acc[mt][nt], ahi[mt], bh0, bh1);
                mma_bf16(acc[mt][nt], ahi[mt], bl0, bl1);
                mma_bf16(acc[mt][nt], alo[mt], bh0, bh1);
            }
        }
    }

    // ---- epilogue: direct STG.64 (quad writes 32B contiguous) -------------
#pragma unroll
    for (int mt = 0; mt < 2; mt++) {
        int r0 = row_base + m_base + mt * 16 + g;
#pragma unroll
        for (int nt = 0; nt < 8; nt++) {
            int n = n_base + nt * 8 + t4 * 2;
            if (r0 < M)
                *(float2*)(C + (size_t)r0 * D + n) =
                    make_float2(acc[mt][nt][0], acc[mt][nt][1]);
            if (r0 + 8 < M)
                *(float2*)(C + (size_t)(r0 + 8) * D + n) =
                    make_float2(acc[mt][nt][2], acc[mt][nt][3]);
        }
    }
}

// ---------------- CSR aggregation: z[n] = sum_{e->n} h[src]*w + self -------
__global__ void __launch_bounds__(256)
k_agg_csr(const float* __restrict__ h, float* __restrict__ z) {
    int gw   = (blockIdx.x * blockDim.x + threadIdx.x) >> 5;
    int lane = threadIdx.x & 31;
    if (gw >= N_NODES) return;
    int n = gw;

    float di = g_dinv[n];
    float ws = di * di;
    float4 hv = ((const float4*)h)[(size_t)n * D4 + lane];
    float4 acc = make_float4(hv.x * ws, hv.y * ws, hv.z * ws, hv.w * ws);

    int s0 = g_rowptr[n];
    int s1 = g_rowptr[n + 1];
    for (int base = s0; base < s1; base += 32) {
        int i = base + lane;
        int2 ed = (i < s1) ? g_csr[i] : make_int2(0, 0);
        int cnt = min(32, s1 - base);
        for (int j = 0; j < cnt; j++) {
            int   sj = __shfl_sync(0xFFFFFFFFu, ed.x, j);
            float wj = __int_as_float(__shfl_sync(0xFFFFFFFFu, ed.y, j));
            float4 v = ((const float4*)h)[(size_t)sj * D4 + lane];
            acc.x = fmaf(v.x, wj, acc.x);
            acc.y = fmaf(v.y, wj, acc.y);
            acc.z = fmaf(v.z, wj, acc.z);
            acc.w = fmaf(v.w, wj, acc.w);
        }
    }
    ((float4*)z)[(size_t)n * D4 + lane] = acc;
}

// ---------------- decode: logits[e] = dot(z[s]+b2, z[d]+b2) ----------------
__global__ void __launch_bounds__(256) k_decode(const void* __restrict__ lab,
                                                const float* __restrict__ b2,
                                                float* __restrict__ out) {
    int gwarp  = (blockIdx.x * blockDim.x + threadIdx.x) >> 5;
    int lane   = threadIdx.x & 31;
    int nwarps = (gridDim.x * blockDim.x) >> 5;
    float4 b = ((const float4*)b2)[lane];
    for (int e = gwarp; e < N_LAB; e += nwarps) {
        int s = load_idx(lab, e);
        int d = load_idx(lab, (size_t)N_LAB + e);
        float4 a = ((const float4*)g_z)[(size_t)s * D4 + lane];
        float4 c = ((const float4*)g_z)[(size_t)d * D4 + lane];
        float sum = (a.x + b.x) * (c.x + b.x)
                  + (a.y + b.y) * (c.y + b.y)
                  + (a.z + b.z) * (c.z + b.z)
                  + (a.w + b.w) * (c.w + b.w);
#pragma unroll
        for (int off = 16; off; off >>= 1)
            sum += __shfl_xor_sync(0xFFFFFFFFu, sum, off);
        if (lane == 0) out[e] = sum;
    }
}

// ---------------- launch ---------------------------------------------------
extern "C" void kernel_launch(void* const* d_in, const int* in_sizes, int n_in,
                              void* d_out, int out_size) {
    const float* x   = (const float*)d_in[0];
    const void*  ei  = d_in[1];               // int32 or int64, autodetected
    const void*  lab = d_in[2];
    const float* W1  = (const float*)d_in[3];
    const float* b1  = (const float*)d_in[4];
    const float* W2  = (const float*)d_in[5];
    const float* b2  = (const float*)d_in[6];
    float*       out = (float*)d_out;

    (void)in_sizes; (void)n_in; (void)out_size;

    cudaFuncSetAttribute(k_gemm_mma, cudaFuncAttributeMaxDynamicSharedMemorySize,
                         MMA_SMEM);

    float *hptr = nullptr, *zptr = nullptr;
    cudaGetSymbolAddress((void**)&hptr, g_h);
    cudaGetSymbolAddress((void**)&zptr, g_z);

    const int T = 256;
    const int NODE_BLOCKS = (N_NODES + T - 1) / T;            // 391
    const int EDGE_BLOCKS = (N_EDGES + T - 1) / T;
    const int GEMM_BLOCKS = (N_NODES + 127) / 128;            // 782
    const int AGG_BLOCKS  = (N_NODES + 7) / 8;                // warp per node
    const int DEC_BLOCKS  = 1184;

    // ---- prep: dtype detect, degrees, norms, CSR build (once per call) ----
    k_detect    <<<1, 32>>>((const int*)ei);
    k_cnt_init  <<<NODE_BLOCKS, T>>>();
    k_cnt_acc   <<<EDGE_BLOCKS, T>>>(ei);
    k_dinv      <<<NODE_BLOCKS, T>>>();
    k_scan_block<<<NB, 256>>>();
    k_scan_top  <<<1, 512>>>();
    k_scan_add  <<<NODE_BLOCKS, T>>>();
    k_fill      <<<EDGE_BLOCKS, T>>>(ei);

    // ---- layer 1: h = x @ W1 ; z = sym-norm aggregate (atomic-free) -------
    k_gemm_mma<<<GEMM_BLOCKS, T, MMA_SMEM>>>(x, W1, nullptr, 0, hptr, N_NODES);
    k_agg_csr <<<AGG_BLOCKS, T>>>(hptr, zptr);

    // ---- layer 2: h = relu(z + b1) @ W2 ; z = aggregate (b2 in decode) ----
    k_gemm_mma<<<GEMM_BLOCKS, T, MMA_SMEM>>>(zptr, W2, b1, 1, hptr, N_NODES);
    k_agg_csr <<<AGG_BLOCKS, T>>>(hptr, zptr);

    // ---- decode -----------------------------------------------------------
    k_decode<<<DEC_BLOCKS, T>>>(lab, b2, out);
}

// round 10
// speedup vs baseline: 3.3963x; 1.0898x over previous
#include <cuda_runtime.h>
#include <cuda_bf16.h>
#include <cstdint>

#define N_NODES 100000
#define N_EDGES 1600000
#define N_LAB   200000
#define D       128
#define D4      32    // D/4 floats
#define DW      64    // D/2 = 32-bit words per row of bf16
#define NB      391   // ceil(N_NODES / 256)
#define NPAD    100096  // 782 * 128, rows padded to CTA tile
#define GEMM_CTAS 782

// ---------------- static device scratch (no allocations allowed) ----------
__device__ float    g_h[(size_t)N_NODES * D];  // GEMM output (pre-aggregation)
__device__ float    g_z[(size_t)N_NODES * D];  // final aggregated features
__device__ float    g_dinv[N_NODES];
__device__ int      g_cnt[N_NODES];
__device__ int      g_rowptr[N_NODES + 1];
__device__ int      g_cursor[N_NODES];
__device__ int      g_bsum[NB];
__device__ int      g_boff[NB];
__device__ int2     g_csr[N_EDGES];            // {src, bitcast(norm weight)}
__device__ int      g_is64;
// split-bf16 operand tables (packed 2xbf16 per word, row-major (r, kword))
__device__ uint32_t g_ahi[(size_t)NPAD * DW];
__device__ uint32_t g_alo[(size_t)NPAD * DW];
__device__ uint32_t g_w1hi[D * DW], g_w1lo[D * DW];  // (n, kword)
__device__ uint32_t g_w2hi[D * DW], g_w2lo[D * DW];

// ---------------- helpers --------------------------------------------------
__device__ __forceinline__ void split_pack(float v0, float v1,
                                           uint32_t& hi, uint32_t& lo) {
    __nv_bfloat16 h0 = __float2bfloat16(v0);
    __nv_bfloat16 h1 = __float2bfloat16(v1);
    __nv_bfloat16 l0 = __float2bfloat16(v0 - __bfloat162float(h0));
    __nv_bfloat16 l1 = __float2bfloat16(v1 - __bfloat162float(h1));
    hi = (uint32_t)__bfloat16_as_ushort(h0) |
         ((uint32_t)__bfloat16_as_ushort(h1) << 16);
    lo = (uint32_t)__bfloat16_as_ushort(l0) |
         ((uint32_t)__bfloat16_as_ushort(l1) << 16);
}

// ---------------- dtype autodetect ----------------------------------------
__global__ void k_detect(const int* __restrict__ ei_raw) {
    if (threadIdx.x == 0 && blockIdx.x == 0) {
        int all_zero = 1;
        for (int i = 0; i < 32; i++)
            if (ei_raw[2 * i + 1] != 0) { all_zero = 0; break; }
        g_is64 = all_zero;
    }
}

__device__ __forceinline__ int load_idx(const void* p, size_t i) {
    return g_is64 ? (int)((const long long*)p)[i] : ((const int*)p)[i];
}

// ---------------- degree / norm prep --------------------------------------
__global__ void k_cnt_init() {
    int i = blockIdx.x * blockDim.x + threadIdx.x;
    if (i < N_NODES) g_cnt[i] = 0;
}

__global__ void k_cnt_acc(const void* __restrict__ ei) {
    int e = blockIdx.x * blockDim.x + threadIdx.x;
    if (e < N_EDGES) atomicAdd(&g_cnt[load_idx(ei, (size_t)N_EDGES + e)], 1);
}

__global__ void k_dinv() {
    int i = blockIdx.x * blockDim.x + threadIdx.x;
    if (i < N_NODES) g_dinv[i] = rsqrtf((float)(g_cnt[i] + 1));  // +1 self loop
}

// ---------------- CSR build: 3-kernel prefix sum + binned fill -------------
__global__ void k_scan_block() {
    __shared__ int sm[256];
    int b = blockIdx.x, t = threadIdx.x;
    int i = b * 256 + t;
    int v = (i < N_NODES) ? g_cnt[i] : 0;
    sm[t] = v;
    __syncthreads();
    for (int off = 1; off < 256; off <<= 1) {
        int add = (t >= off) ? sm[t - off] : 0;
        __syncthreads();
        sm[t] += add;
        __syncthreads();
    }
    if (i < N_NODES) g_rowptr[i] = sm[t] - v;
    if (t == 255)    g_bsum[b] = sm[255];
}

__global__ void k_scan_top() {
    __shared__ int sm[512];
    int t = threadIdx.x;
    int v = (t < NB) ? g_bsum[t] : 0;
    sm[t] = v;
    __syncthreads();
    for (int off = 1; off < 512; off <<= 1) {
        int add = (t >= off) ? sm[t - off] : 0;
        __syncthreads();
        sm[t] += add;
        __syncthreads();
    }
    if (t < NB) g_boff[t] = sm[t] - v;
    if (t == 0) g_rowptr[N_NODES] = sm[511];
}

__global__ void k_scan_add() {
    int i = blockIdx.x * blockDim.x + threadIdx.x;
    if (i < N_NODES) {
        int r = g_rowptr[i] + g_boff[i >> 8];
        g_rowptr[i] = r;
        g_cursor[i] = r;
    }
}

__global__ void k_fill(const void* __restrict__ ei) {
    int e = blockIdx.x * blockDim.x + threadIdx.x;
    if (e < N_EDGES) {
        int s = load_idx(ei, e);
        int d = load_idx(ei, (size_t)N_EDGES + e);
        float w = g_dinv[s] * g_dinv[d];
        int pos = atomicAdd(&g_cursor[d], 1);
        g_csr[pos] = make_int2(s, __float_as_int(w));
    }
}

// ---------------- operand conversion (once per call) -----------------------
// x -> split-bf16 word tables; padded rows zero-filled.
__global__ void k_xconv(const float* __restrict__ x) {
    int idx = blockIdx.x * 256 + threadIdx.x;      // word index
    int r = idx >> 6, wcol = idx & 63;
    float2 v = (r < N_NODES) ? ((const float2*)x)[(size_t)r * DW + wcol]
                             : make_float2(0.f, 0.f);
    uint32_t hi, lo;
    split_pack(v.x, v.y, hi, lo);
    g_ahi[idx] = hi;
    g_alo[idx] = lo;
}

// W1, W2 -> transposed (n, kword) split-bf16 fragment tables.
__global__ void k_wconv(const float* __restrict__ W1,
                        const float* __restrict__ W2) {
    int idx = blockIdx.x * 256 + threadIdx.x;      // 0..16383
    int mat = idx >> 13;
    int j = idx & 8191;
    int n = j >> 6, kw = j & 63;
    const float* Wm = mat ? W2 : W1;
    float v0 = Wm[(size_t)(2 * kw) * D + n];
    float v1 = Wm[(size_t)(2 * kw + 1) * D + n];
    uint32_t hi, lo;
    split_pack(v0, v1, hi, lo);
    if (mat) { g_w2hi[j] = hi; g_w2lo[j] = lo; }
    else     { g_w1hi[j] = hi; g_w1lo[j] = lo; }
}

// ================= HMMA GEMM (mma.sync, split-bf16 x3, LDG-only) ===========
// C[M,128] = A @ W with A,W pre-converted to hi/lo bf16 word tables.
// CTA: 128 rows x 128 cols, 256 threads (4 M-groups x 2 N-groups of warps).
// No smem, no syncthreads; operands stream through L1 (128 KB/CTA set).
__device__ __forceinline__ void mma_bf16(float* d, const uint32_t* a,
                                         uint32_t b0, uint32_t b1) {
    asm volatile(
        "mma.sync.aligned.m16n8k16.row.col.f32.bf16.bf16.f32 "
        "{%0,%1,%2,%3}, {%4,%5,%6,%7}, {%8,%9}, {%0,%1,%2,%3};"
        : "+f"(d[0]), "+f"(d[1]), "+f"(d[2]), "+f"(d[3])
        : "r"(a[0]), "r"(a[1]), "r"(a[2]), "r"(a[3]), "r"(b0), "r"(b1));
}

__global__ void __launch_bounds__(256, 2)
k_gemm_mma(const uint32_t* __restrict__ Bhi, const uint32_t* __restrict__ Blo,
           float* __restrict__ C, int M) {
    int tid = threadIdx.x, wid = tid >> 5, lane = tid & 31;
    int g = lane >> 2, t4 = lane & 3;
    int m0 = blockIdx.x * 128 + (wid & 3) * 32;    // this warp's first row
    int n_base = (wid >> 2) * 64;

    float acc[2][8][4];
#pragma unroll
    for (int mt = 0; mt < 2; mt++)
#pragma unroll
        for (int nt = 0; nt < 8; nt++)
#pragma unroll
            for (int j = 0; j < 4; j++) acc[mt][nt][j] = 0.f;

#pragma unroll
    for (int ks = 0; ks < 8; ks++) {
        int kw = ks * 8 + t4;
        uint32_t ahi[2][4], alo[2][4];
#pragma unroll
        for (int mt = 0; mt < 2; mt++) {
            size_t base = (size_t)(m0 + mt * 16 + g) * DW + kw;
            ahi[mt][0] = __ldg(g_ahi + base);
            ahi[mt][1] = __ldg(g_ahi + base + 8 * DW);
            ahi[mt][2] = __ldg(g_ahi + base + 4);
            ahi[mt][3] = __ldg(g_ahi + base + 8 * DW + 4);
            alo[mt][0] = __ldg(g_alo + base);
            alo[mt][1] = __ldg(g_alo + base + 8 * DW);
            alo[mt][2] = __ldg(g_alo + base + 4);
            alo[mt][3] = __ldg(g_alo + base + 8 * DW + 4);
        }
#pragma unroll
        for (int nt = 0; nt < 8; nt++) {
            size_t nb = (size_t)(n_base + nt * 8 + g) * DW + kw;
            uint32_t bh0 = __ldg(Bhi + nb);
            uint32_t bh1 = __ldg(Bhi + nb + 4);
            uint32_t bl0 = __ldg(Blo + nb);
            uint32_t bl1 = __ldg(Blo + nb + 4);
#pragma unroll
            for (int mt = 0; mt < 2; mt++) {
                mma_bf16(acc[mt][nt], ahi[mt], bh0, bh1);
                mma_bf16(acc[mt][nt], ahi[mt], bl0, bl1);
                mma_bf16(acc[mt][nt], alo[mt], bh0, bh1);
            }
        }
    }

#pragma unroll
    for (int mt = 0; mt < 2; mt++) {
        int r0 = m0 + mt * 16 + g;
#pragma unroll
        for (int nt = 0; nt < 8; nt++) {
            int n = n_base + nt * 8 + t4 * 2;
            if (r0 < M)
                *(float2*)(C + (size_t)r0 * D + n) =
                    make_float2(acc[mt][nt][0], acc[mt][nt][1]);
            if (r0 + 8 < M)
                *(float2*)(C + (size_t)(r0 + 8) * D + n) =
                    make_float2(acc[mt][nt][2], acc[mt][nt][3]);
        }
    }
}

// ---------------- CSR aggregation: z[n] = sum_{e->n} h[src]*w + self -------
// conv_mode=1: instead of fp32 z, write relu(z + bias) as split-bf16 into the
// A tables (feeds the next GEMM directly). conv_mode=0: write fp32 z.
__global__ void __launch_bounds__(256)
k_agg_csr(const float* __restrict__ h, float* __restrict__ z,
          const float* __restrict__ bias, int conv_mode) {
    int gw   = (blockIdx.x * blockDim.x + threadIdx.x) >> 5;
    int lane = threadIdx.x & 31;
    if (gw >= N_NODES) return;
    int n = gw;

    float di = g_dinv[n];
    float ws = di * di;
    float4 hv = ((const float4*)h)[(size_t)n * D4 + lane];
    float4 acc = make_float4(hv.x * ws, hv.y * ws, hv.z * ws, hv.w * ws);

    int s0 = g_rowptr[n];
    int s1 = g_rowptr[n + 1];
    for (int base = s0; base < s1; base += 32) {
        int i = base + lane;
        int2 ed = (i < s1) ? g_csr[i] : make_int2(0, 0);
        int cnt = min(32, s1 - base);
        for (int j = 0; j < cnt; j++) {
            int   sj = __shfl_sync(0xFFFFFFFFu, ed.x, j);
            float wj = __int_as_float(__shfl_sync(0xFFFFFFFFu, ed.y, j));
            float4 v = ((const float4*)h)[(size_t)sj * D4 + lane];
            acc.x = fmaf(v.x, wj, acc.x);
            acc.y = fmaf(v.y, wj, acc.y);
            acc.z = fmaf(v.z, wj, acc.z);
            acc.w = fmaf(v.w, wj, acc.w);
        }
    }

    if (conv_mode) {
        float4 b = ((const float4*)bias)[lane];
        float v0 = fmaxf(acc.x + b.x, 0.f);
        float v1 = fmaxf(acc.y + b.y, 0.f);
        float v2 = fmaxf(acc.z + b.z, 0.f);
        float v3 = fmaxf(acc.w + b.w, 0.f);
        uint32_t hi0, lo0, hi1, lo1;
        split_pack(v0, v1, hi0, lo0);
        split_pack(v2, v3, hi1, lo1);
        size_t base = (size_t)n * DW + lane * 2;
        g_ahi[base]     = hi0;
        g_ahi[base + 1] = hi1;
        g_alo[base]     = lo0;
        g_alo[base + 1] = lo1;
    } else {
        ((float4*)z)[(size_t)n * D4 + lane] = acc;
    }
}

// ---------------- decode: logits[e] = dot(z[s]+b2, z[d]+b2) ----------------
__global__ void __launch_bounds__(256) k_decode(const void* __restrict__ lab,
                                                const float* __restrict__ b2,
                                                float* __restrict__ out) {
    int gwarp  = (blockIdx.x * blockDim.x + threadIdx.x) >> 5;
    int lane   = threadIdx.x & 31;
    int nwarps = (gridDim.x * blockDim.x) >> 5;
    float4 b = ((const float4*)b2)[lane];
    for (int e = gwarp; e < N_LAB; e += nwarps) {
        int s = load_idx(lab, e);
        int d = load_idx(lab, (size_t)N_LAB + e);
        float4 a = ((const float4*)g_z)[(size_t)s * D4 + lane];
        float4 c = ((const float4*)g_z)[(size_t)d * D4 + lane];
        float sum = (a.x + b.x) * (c.x + b.x)
                  + (a.y + b.y) * (c.y + b.y)
                  + (a.z + b.z) * (c.z + b.z)
                  + (a.w + b.w) * (c.w + b.w);
#pragma unroll
        for (int off = 16; off; off >>= 1)
            sum += __shfl_xor_sync(0xFFFFFFFFu, sum, off);
        if (lane == 0) out[e] = sum;
    }
}

// ---------------- launch ---------------------------------------------------
extern "C" void kernel_launch(void* const* d_in, const int* in_sizes, int n_in,
                              void* d_out, int out_size) {
    const float* x   = (const float*)d_in[0];
    const void*  ei  = d_in[1];               // int32 or int64, autodetected
    const void*  lab = d_in[2];
    const float* W1  = (const float*)d_in[3];
    const float* b1  = (const float*)d_in[4];
    const float* W2  = (const float*)d_in[5];
    const float* b2  = (const float*)d_in[6];
    float*       out = (float*)d_out;

    (void)in_sizes; (void)n_in; (void)out_size;

    static cudaStream_t side = nullptr;
    static cudaEvent_t  e_fork = nullptr, e_join = nullptr;
    if (!side) {
        cudaStreamCreate(&side);
        cudaEventCreateWithFlags(&e_fork, cudaEventDisableTiming);
        cudaEventCreateWithFlags(&e_join, cudaEventDisableTiming);
    }

    float *hptr = nullptr, *zptr = nullptr;
    uint32_t *w1hi, *w1lo, *w2hi, *w2lo;
    cudaGetSymbolAddress((void**)&hptr, g_h);
    cudaGetSymbolAddress((void**)&zptr, g_z);
    cudaGetSymbolAddress((void**)&w1hi, g_w1hi);
    cudaGetSymbolAddress((void**)&w1lo, g_w1lo);
    cudaGetSymbolAddress((void**)&w2hi, g_w2hi);
    cudaGetSymbolAddress((void**)&w2lo, g_w2lo);

    const int T = 256;
    const int NODE_BLOCKS = (N_NODES + T - 1) / T;   // 391
    const int EDGE_BLOCKS = (N_EDGES + T - 1) / T;
    const int XCONV_BLOCKS = NPAD * DW / T;          // 25024
    const int AGG_BLOCKS  = (N_NODES + 7) / 8;
    const int DEC_BLOCKS  = 1184;

    // ---- fork: prep chain on side stream (independent of GEMM path) ------
    cudaEventRecord(e_fork, 0);
    cudaStreamWaitEvent(side, e_fork, 0);
    k_detect    <<<1, 32, 0, side>>>((const int*)ei);
    k_cnt_init  <<<NODE_BLOCKS, T, 0, side>>>();
    k_cnt_acc   <<<EDGE_BLOCKS, T, 0, side>>>(ei);
    k_dinv      <<<NODE_BLOCKS, T, 0, side>>>();
    k_scan_block<<<NB, 256, 0, side>>>();
    k_scan_top  <<<1, 512, 0, side>>>();
    k_scan_add  <<<NODE_BLOCKS, T, 0, side>>>();
    k_fill      <<<EDGE_BLOCKS, T, 0, side>>>(ei);
    cudaEventRecord(e_join, side);

    // ---- main stream: convert operands, GEMM layer 1 ----------------------
    k_wconv   <<<64, T>>>(W1, W2);
    k_xconv   <<<XCONV_BLOCKS, T>>>(x);
    k_gemm_mma<<<GEMM_CTAS, T>>>(w1hi, w1lo, hptr, N_NODES);

    // ---- join, then aggregate (writes next layer's A tables fused) --------
    cudaStreamWaitEvent(0, e_join, 0);
    k_agg_csr<<<AGG_BLOCKS, T>>>(hptr, zptr, b1, 1);

    // ---- layer 2 GEMM + aggregation ---------------------------------------
    k_gemm_mma<<<GEMM_CTAS, T>>>(w2hi, w2lo, hptr, N_NODES);
    k_agg_csr<<<AGG_BLOCKS, T>>>(hptr, zptr, nullptr, 0);

    // ---- decode -----------------------------------------------------------
    k_decode<<<DEC_BLOCKS, T>>>(lab, b2, out);
}

// round 13
// speedup vs baseline: 3.5848x; 1.0555x over previous
#include <cuda_runtime.h>
#include <cuda_bf16.h>
#include <cstdint>

#define N_NODES 100000
#define N_EDGES 1600000
#define N_LAB   200000
#define D       128
#define D4      32    // D/4 floats
#define DW      64    // D/2 = 32-bit words per row of bf16
#define NB      391   // ceil(N_NODES / 256)
#define GEMM_CTAS 782
#define NHALF   50048 // 391 * 128 (CTA-aligned node split)

// ---------------- static device scratch (no allocations allowed) ----------
__device__ float    g_h[(size_t)N_NODES * D];  // GEMM output (pre-aggregation)
__device__ float    g_z[(size_t)N_NODES * D];  // final aggregated features
__device__ float    g_dinv[N_NODES];
__device__ int      g_cnt[N_NODES];
__device__ int      g_rowptr[N_NODES + 1];
__device__ int      g_cursor[N_NODES];
__device__ int      g_bsum[NB];
__device__ int      g_boff[NB];
__device__ int2     g_csr[N_EDGES];            // {src, bitcast(norm weight)}
__device__ int      g_is64;
// split-bf16 A tables for layer 2 (written by agg1; padding rows stay 0)
__device__ uint32_t g_ahi[(size_t)GEMM_CTAS * 128 * DW];
__device__ uint32_t g_alo[(size_t)GEMM_CTAS * 128 * DW];
__device__ uint32_t g_w1hi[D * DW], g_w1lo[D * DW];  // (n, kword)
__device__ uint32_t g_w2hi[D * DW], g_w2lo[D * DW];

// ---------------- helpers --------------------------------------------------
__device__ __forceinline__ void split_pack(float v0, float v1,
                                           uint32_t& hi, uint32_t& lo) {
    __nv_bfloat16 h0 = __float2bfloat16(v0);
    __nv_bfloat16 h1 = __float2bfloat16(v1);
    __nv_bfloat16 l0 = __float2bfloat16(v0 - __bfloat162float(h0));
    __nv_bfloat16 l1 = __float2bfloat16(v1 - __bfloat162float(h1));
    hi = (uint32_t)__bfloat16_as_ushort(h0) |
         ((uint32_t)__bfloat16_as_ushort(h1) << 16);
    lo = (uint32_t)__bfloat16_as_ushort(l0) |
         ((uint32_t)__bfloat16_as_ushort(l1) << 16);
}

// ---------------- dtype autodetect + counter init (fused) ------------------
__global__ void k_detect_init(const int* __restrict__ ei_raw) {
    int i = blockIdx.x * blockDim.x + threadIdx.x;
    if (i < N_NODES) g_cnt[i] = 0;
    if (i == 0) {
        int all_zero = 1;
        for (int j = 0; j < 32; j++)
            if (ei_raw[2 * j + 1] != 0) { all_zero = 0; break; }
        g_is64 = all_zero;
    }
}

__device__ __forceinline__ int load_idx(const void* p, size_t i) {
    return g_is64 ? (int)((const long long*)p)[i] : ((const int*)p)[i];
}

// ---------------- degree / norm prep --------------------------------------
__global__ void k_cnt_acc(const void* __restrict__ ei) {
    int e = blockIdx.x * blockDim.x + threadIdx.x;
    if (e < N_EDGES) atomicAdd(&g_cnt[load_idx(ei, (size_t)N_EDGES + e)], 1);
}

__global__ void k_dinv() {
    int i = blockIdx.x * blockDim.x + threadIdx.x;
    if (i < N_NODES) g_dinv[i] = rsqrtf((float)(g_cnt[i] + 1));  // +1 self loop
}

// ---------------- CSR build: 3-kernel prefix sum + binned fill -------------
__global__ void k_scan_block() {
    __shared__ int sm[256];
    int b = blockIdx.x, t = threadIdx.x;
    int i = b * 256 + t;
    int v = (i < N_NODES) ? g_cnt[i] : 0;
    sm[t] = v;
    __syncthreads();
    for (int off = 1; off < 256; off <<= 1) {
        int add = (t >= off) ? sm[t - off] : 0;
        __syncthreads();
        sm[t] += add;
        __syncthreads();
    }
    if (i < N_NODES) g_rowptr[i] = sm[t] - v;
    if (t == 255)    g_bsum[b] = sm[255];
}

__global__ void k_scan_top() {
    __shared__ int sm[512];
    int t = threadIdx.x;
    int v = (t < NB) ? g_bsum[t] : 0;
    sm[t] = v;
    __syncthreads();
    for (int off = 1; off < 512; off <<= 1) {
        int add = (t >= off) ? sm[t - off] : 0;
        __syncthreads();
        sm[t] += add;
        __syncthreads();
    }
    if (t < NB) g_boff[t] = sm[t] - v;
    if (t == 0) g_rowptr[N_NODES] = sm[511];
}

__global__ void k_scan_add() {
    int i = blockIdx.x * blockDim.x + threadIdx.x;
    if (i < N_NODES) {
        int r = g_rowptr[i] + g_boff[i >> 8];
        g_rowptr[i] = r;
        g_cursor[i] = r;
    }
}

__global__ void k_fill(const void* __restrict__ ei) {
    int e = blockIdx.x * blockDim.x + threadIdx.x;
    if (e < N_EDGES) {
        int s = load_idx(ei, e);
        int d = load_idx(ei, (size_t)N_EDGES + e);
        float w = g_dinv[s] * g_dinv[d];
        int pos = atomicAdd(&g_cursor[d], 1);
        g_csr[pos] = make_int2(s, __float_as_int(w));
    }
}

// ---------------- W conversion (once per call, tiny) -----------------------
__global__ void k_wconv(const float* __restrict__ W1,
                        const float* __restrict__ W2) {
    int idx = blockIdx.x * 256 + threadIdx.x;      // 0..16383
    int mat = idx >> 13;
    int j = idx & 8191;
    int n = j >> 6, kw = j & 63;
    const float* Wm = mat ? W2 : W1;
    float v0 = Wm[(size_t)(2 * kw) * D + n];
    float v1 = Wm[(size_t)(2 * kw + 1) * D + n];
    uint32_t hi, lo;
    split_pack(v0, v1, hi, lo);
    if (mat) { g_w2hi[j] = hi; g_w2lo[j] = lo; }
    else     { g_w1hi[j] = hi; g_w1lo[j] = lo; }
}

// ================= HMMA GEMM (mma.sync, split-bf16 x3) =====================
__device__ __forceinline__ void mma_bf16(float* d, const uint32_t* a,
                                         uint32_t b0, uint32_t b1) {
    asm volatile(
        "mma.sync.aligned.m16n8k16.row.col.f32.bf16.bf16.f32 "
        "{%0,%1,%2,%3}, {%4,%5,%6,%7}, {%8,%9}, {%0,%1,%2,%3};"
        : "+f"(d[0]), "+f"(d[1]), "+f"(d[2]), "+f"(d[3])
        : "r"(a[0]), "r"(a[1]), "r"(a[2]), "r"(a[3]), "r"(b0), "r"(b1));
}

// Common body: fragments provided by LOADA macro expansion via lambdas is
// ugly in CUDA; duplicate the mainloop in two kernels instead.

// Layer-1 GEMM: A = fp32 x, converted to split-bf16 in-register.
__global__ void __launch_bounds__(256, 2)
k_gemm_x(const float* __restrict__ X,
         const uint32_t* __restrict__ Bhi, const uint32_t* __restrict__ Blo,
         float* __restrict__ C, int M) {
    int tid = threadIdx.x, wid = tid >> 5, lane = tid & 31;
    int g = lane >> 2, t4 = lane & 3;
    int m0 = blockIdx.x * 128 + (wid & 3) * 32;
    int n_base = (wid >> 2) * 64;
    const float2* x2 = (const float2*)X;

    float acc[2][8][4];
#pragma unroll
    for (int mt = 0; mt < 2; mt++)
#pragma unroll
        for (int nt = 0; nt < 8; nt++)
#pragma unroll
            for (int j = 0; j < 4; j++) acc[mt][nt][j] = 0.f;

#pragma unroll
    for (int ks = 0; ks < 8; ks++) {
        int kw = ks * 8 + t4;
        uint32_t ahi[2][4], alo[2][4];
#pragma unroll
        for (int mt = 0; mt < 2; mt++) {
            int r = m0 + mt * 16 + g;
            float2 z2 = make_float2(0.f, 0.f);
            float2 v0 = (r < M)     ? __ldg(x2 + (size_t)r * DW + kw)           : z2;
            float2 v1 = (r + 8 < M) ? __ldg(x2 + (size_t)(r + 8) * DW + kw)     : z2;
            float2 v2 = (r < M)     ? __ldg(x2 + (size_t)r * DW + kw + 4)       : z2;
            float2 v3 = (r + 8 < M) ? __ldg(x2 + (size_t)(r + 8) * DW + kw + 4) : z2;
            split_pack(v0.x, v0.y, ahi[mt][0], alo[mt][0]);
            split_pack(v1.x, v1.y, ahi[mt][1], alo[mt][1]);
            split_pack(v2.x, v2.y, ahi[mt][2], alo[mt][2]);
            split_pack(v3.x, v3.y, ahi[mt][3], alo[mt][3]);
        }
#pragma unroll
        for (int nt = 0; nt < 8; nt++) {
            size_t nb = (size_t)(n_base + nt * 8 + g) * DW + kw;
            uint32_t bh0 = __ldg(Bhi + nb);
            uint32_t bh1 = __ldg(Bhi + nb + 4);
            uint32_t bl0 = __ldg(Blo + nb);
            uint32_t bl1 = __ldg(Blo + nb + 4);
#pragma unroll
            for (int mt = 0; mt < 2; mt++) {
                mma_bf16(acc[mt][nt], ahi[mt], bh0, bh1);
                mma_bf16(acc[mt][nt], ahi[mt], bl0, bl1);
                mma_bf16(acc[mt][nt], alo[mt], bh0, bh1);
            }
        }
    }

#pragma unroll
    for (int mt = 0; mt < 2; mt++) {
        int r0 = m0 + mt * 16 + g;
#pragma unroll
        for (int nt = 0; nt < 8; nt++) {
            int n = n_base + nt * 8 + t4 * 2;
            if (r0 < M)
                *(float2*)(C + (size_t)r0 * D + n) =
                    make_float2(acc[mt][nt][0], acc[mt][nt][1]);
            if (r0 + 8 < M)
                *(float2*)(C + (size_t)(r0 + 8) * D + n) =
                    make_float2(acc[mt][nt][2], acc[mt][nt][3]);
        }
    }
}

// Layer-2 GEMM: A read from pre-split hi/lo tables; row_off selects the half.
__global__ void __launch_bounds__(256, 2)
k_gemm_mma(const uint32_t* __restrict__ Bhi, const uint32_t* __restrict__ Blo,
           float* __restrict__ C, int M, int row_off) {
    int tid = threadIdx.x, wid = tid >> 5, lane = tid & 31;
    int g = lane >> 2, t4 = lane & 3;
    int m0 = row_off + blockIdx.x * 128 + (wid & 3) * 32;
    int n_base = (wid >> 2) * 64;

    float acc[2][8][4];
#pragma unroll
    for (int mt = 0; mt < 2; mt++)
#pragma unroll
        for (int nt = 0; nt < 8; nt++)
#pragma unroll
            for (int j = 0; j < 4; j++) acc[mt][nt][j] = 0.f;

#pragma unroll
    for (int ks = 0; ks < 8; ks++) {
        int kw = ks * 8 + t4;
        uint32_t ahi[2][4], alo[2][4];
#pragma unroll
        for (int mt = 0; mt < 2; mt++) {
            size_t base = (size_t)(m0 + mt * 16 + g) * DW + kw;
            ahi[mt][0] = __ldg(g_ahi + base);
            ahi[mt][1] = __ldg(g_ahi + base + 8 * DW);
            ahi[mt][2] = __ldg(g_ahi + base + 4);
            ahi[mt][3] = __ldg(g_ahi + base + 8 * DW + 4);
            alo[mt][0] = __ldg(g_alo + base);
            alo[mt][1] = __ldg(g_alo + base + 8 * DW);
            alo[mt][2] = __ldg(g_alo + base + 4);
            alo[mt][3] = __ldg(g_alo + base + 8 * DW + 4);
        }
#pragma unroll
        for (int nt = 0; nt < 8; nt++) {
            size_t nb = (size_t)(n_base + nt * 8 + g) * DW + kw;
            uint32_t bh0 = __ldg(Bhi + nb);
            uint32_t bh1 = __ldg(Bhi + nb + 4);
            uint32_t bl0 = __ldg(Blo + nb);
            uint32_t bl1 = __ldg(Blo + nb + 4);
#pragma unroll
            for (int mt = 0; mt < 2; mt++) {
                mma_bf16(acc[mt][nt], ahi[mt], bh0, bh1);
                mma_bf16(acc[mt][nt], ahi[mt], bl0, bl1);
                mma_bf16(acc[mt][nt], alo[mt], bh0, bh1);
            }
        }
    }

#pragma unroll
    for (int mt = 0; mt < 2; mt++) {
        int r0 = m0 + mt * 16 + g;
#pragma unroll
        for (int nt = 0; nt < 8; nt++) {
            int n = n_base + nt * 8 + t4 * 2;
            if (r0 < M)
                *(float2*)(C + (size_t)r0 * D + n) =
                    make_float2(acc[mt][nt][0], acc[mt][nt][1]);
            if (r0 + 8 < M)
                *(float2*)(C + (size_t)(r0 + 8) * D + n) =
                    make_float2(acc[mt][nt][2], acc[mt][nt][3]);
        }
    }
}

// ---------------- CSR aggregation: z[n] = sum_{e->n} h[src]*w + self -------
// conv_mode=1: write relu(z + bias) as split-bf16 into the A tables.
// node_off lets the caller split the node range for pipelining.
__global__ void __launch_bounds__(256)
k_agg_csr(const float* __restrict__ h, float* __restrict__ z,
          const float* __restrict__ bias, int conv_mode,
          int node_off, int node_end) {
    int gw   = (blockIdx.x * blockDim.x + threadIdx.x) >> 5;
    int lane = threadIdx.x & 31;
    int n = node_off + gw;
    if (n >= node_end) return;

    float di = g_dinv[n];
    float ws = di * di;
    float4 hv = ((const float4*)h)[(size_t)n * D4 + lane];
    float4 acc = make_float4(hv.x * ws, hv.y * ws, hv.z * ws, hv.w * ws);

    int s0 = g_rowptr[n];
    int s1 = g_rowptr[n + 1];
    for (int base = s0; base < s1; base += 32) {
        int i = base + lane;
        int2 ed = (i < s1) ? g_csr[i] : make_int2(0, 0);
        int cnt = min(32, s1 - base);
        for (int j = 0; j < cnt; j++) {
            int   sj = __shfl_sync(0xFFFFFFFFu, ed.x, j);
            float wj = __int_as_float(__shfl_sync(0xFFFFFFFFu, ed.y, j));
            float4 v = ((const float4*)h)[(size_t)sj * D4 + lane];
            acc.x = fmaf(v.x, wj, acc.x);
            acc.y = fmaf(v.y, wj, acc.y);
            acc.z = fmaf(v.z, wj, acc.z);
            acc.w = fmaf(v.w, wj, acc.w);
        }
    }

    if (conv_mode) {
        float4 b = ((const float4*)bias)[lane];
        float v0 = fmaxf(acc.x + b.x, 0.f);
        float v1 = fmaxf(acc.y + b.y, 0.f);
        float v2 = fmaxf(acc.z + b.z, 0.f);
        float v3 = fmaxf(acc.w + b.w, 0.f);
        uint32_t hi0, lo0, hi1, lo1;
        split_pack(v0, v1, hi0, lo0);
        split_pack(v2, v3, hi1, lo1);
        size_t base = (size_t)n * DW + lane * 2;
        g_ahi[base]     = hi0;
        g_ahi[base + 1] = hi1;
        g_alo[base]     = lo0;
        g_alo[base + 1] = lo1;
    } else {
        ((float4*)z)[(size_t)n * D4 + lane] = acc;
    }
}

// ---------------- decode: logits[e] = dot(z[s]+b2, z[d]+b2) ----------------
__global__ void __launch_bounds__(256) k_decode(const void* __restrict__ lab,
                                                const float* __restrict__ b2,
                                                float* __restrict__ out) {
    int gwarp  = (blockIdx.x * blockDim.x + threadIdx.x) >> 5;
    int lane   = threadIdx.x & 31;
    int nwarps = (gridDim.x * blockDim.x) >> 5;
    float4 b = ((const float4*)b2)[lane];
    for (int e = gwarp; e < N_LAB; e += nwarps) {
        int s = load_idx(lab, e);
        int d = load_idx(lab, (size_t)N_LAB + e);
        float4 a = ((const float4*)g_z)[(size_t)s * D4 + lane];
        float4 c = ((const float4*)g_z)[(size_t)d * D4 + lane];
        float sum = (a.x + b.x) * (c.x + b.x)
                  + (a.y + b.y) * (c.y + b.y)
                  + (a.z + b.z) * (c.z + b.z)
                  + (a.w + b.w) * (c.w + b.w);
#pragma unroll
        for (int off = 16; off; off >>= 1)
            sum += __shfl_xor_sync(0xFFFFFFFFu, sum, off);
        if (lane == 0) out[e] = sum;
    }
}

// ---------------- launch ---------------------------------------------------
extern "C" void kernel_launch(void* const* d_in, const int* in_sizes, int n_in,
                              void* d_out, int out_size) {
    const float* x   = (const float*)d_in[0];
    const void*  ei  = d_in[1];               // int32 or int64, autodetected
    const void*  lab = d_in[2];
    const float* W1  = (const float*)d_in[3];
    const float* b1  = (const float*)d_in[4];
    const float* W2  = (const float*)d_in[5];
    const float* b2  = (const float*)d_in[6];
    float*       out = (float*)d_out;

    (void)in_sizes; (void)n_in; (void)out_size;

    static cudaStream_t side = nullptr;
    static cudaEvent_t  e_fork = nullptr, e_join = nullptr,
                        e_aggA = nullptr, e_g2A = nullptr;
    if (!side) {
        cudaStreamCreate(&side);
        cudaEventCreateWithFlags(&e_fork, cudaEventDisableTiming);
        cudaEventCreateWithFlags(&e_join, cudaEventDisableTiming);
        cudaEventCreateWithFlags(&e_aggA, cudaEventDisableTiming);
        cudaEventCreateWithFlags(&e_g2A, cudaEventDisableTiming);
    }

    float *hptr = nullptr, *zptr = nullptr;
    uint32_t *w1hi, *w1lo, *w2hi, *w2lo;
    cudaGetSymbolAddress((void**)&hptr, g_h);
    cudaGetSymbolAddress((void**)&zptr, g_z);
    cudaGetSymbolAddress((void**)&w1hi, g_w1hi);
    cudaGetSymbolAddress((void**)&w1lo, g_w1lo);
    cudaGetSymbolAddress((void**)&w2hi, g_w2hi);
    cudaGetSymbolAddress((void**)&w2lo, g_w2lo);

    const int T = 256;
    const int NODE_BLOCKS = (N_NODES + T - 1) / T;   // 391
    const int EDGE_BLOCKS = (N_EDGES + T - 1) / T;
    const int DEC_BLOCKS  = 1184;
    const int AGG_A = NHALF / 8;                     // 6256
    const int AGG_B = (N_NODES - NHALF + 7) / 8;     // 6244
    const int G2_A  = NHALF / 128;                   // 391
    const int G2_B  = GEMM_CTAS - G2_A;              // 391

    // ---- fork: prep chain on side stream ----------------------------------
    cudaEventRecord(e_fork, 0);
    cudaStreamWaitEvent(side, e_fork, 0);
    k_detect_init<<<NODE_BLOCKS, T, 0, side>>>((const int*)ei);
    k_cnt_acc    <<<EDGE_BLOCKS, T, 0, side>>>(ei);
    k_dinv       <<<NODE_BLOCKS, T, 0, side>>>();
    k_scan_block <<<NB, 256, 0, side>>>();
    k_scan_top   <<<1, 512, 0, side>>>();
    k_scan_add   <<<NODE_BLOCKS, T, 0, side>>>();
    k_fill       <<<EDGE_BLOCKS, T, 0, side>>>(ei);
    cudaEventRecord(e_join, side);

    // ---- main stream: W conversion + layer-1 GEMM (fp32-fused) ------------
    k_wconv <<<64, T>>>(W1, W2);
    k_gemm_x<<<GEMM_CTAS, T>>>(x, w1hi, w1lo, hptr, N_NODES);

    // ---- join, then agg1 first half; gemm2 first half overlaps agg1_B -----
    cudaStreamWaitEvent(0, e_join, 0);
    k_agg_csr<<<AGG_A, T>>>(hptr, zptr, b1, 1, 0, NHALF);
    cudaEventRecord(e_aggA, 0);

    cudaStreamWaitEvent(side, e_aggA, 0);
    k_gemm_mma<<<G2_A, T, 0, side>>>(w2hi, w2lo, hptr, N_NODES, 0);
    cudaEventRecord(e_g2A, side);

    k_agg_csr <<<AGG_B, T>>>(hptr, zptr, b1, 1, NHALF, N_NODES);
    k_gemm_mma<<<G2_B, T>>>(w2hi, w2lo, hptr, N_NODES, NHALF);
    cudaStreamWaitEvent(0, e_g2A, 0);

    // ---- agg2 + decode -----------------------------------------------------
    k_agg_csr<<<(N_NODES + 7) / 8, T>>>(hptr, zptr, nullptr, 0, 0, N_NODES);
    k_decode <<<DEC_BLOCKS, T>>>(lab, b2, out);
}